// round 4
// baseline (speedup 1.0000x reference)
#include <cuda_runtime.h>
#include <math.h>

// Flow_49546742727298: CNF Euler, exact divergence via analytic trace.
// R4: MSAMP=4 (ILP over occupancy), halved LDS, csum trick, precomputed bse.

#define THREADS 128
#define MSAMP   4
#define NSTEPS  2
#define ROWF    36

typedef unsigned long long u64;

__device__ __forceinline__ u64 fma2(u64 a, u64 b, u64 c) {
    u64 d; asm("fma.rn.f32x2 %0, %1, %2, %3;" : "=l"(d) : "l"(a), "l"(b), "l"(c)); return d;
}
__device__ __forceinline__ u64 mul2(u64 a, u64 b) {
    u64 d; asm("mul.rn.f32x2 %0, %1, %2;" : "=l"(d) : "l"(a), "l"(b)); return d;
}
__device__ __forceinline__ u64 add2(u64 a, u64 b) {
    u64 d; asm("add.rn.f32x2 %0, %1, %2;" : "=l"(d) : "l"(a), "l"(b)); return d;
}
__device__ __forceinline__ u64 pack2(float lo, float hi) {
    u64 d; asm("mov.b64 %0, {%1, %2};" : "=l"(d) : "f"(lo), "f"(hi)); return d;
}
__device__ __forceinline__ void unpack2(u64 p, float& lo, float& hi) {
    asm("mov.b64 {%0, %1}, %2;" : "=f"(lo), "=f"(hi) : "l"(p));
}
__device__ __forceinline__ float fast_tanh(float x) {
    float y; asm("tanh.approx.f32 %0, %1;" : "=f"(y) : "f"(x)); return y;
}

// Shared row j (36 floats, 144B):
//  [0..15]  W1[0..15][j]   (i-pairs consecutive -> u64 f32x2 operands)
//  [16] bse0 = b1[j]            (pre-activation bias at t=0)
//  [17] bse1 = b1[j]+0.5*wt[j]  (pre-activation bias at t=0.5)
//  [18] c[j] = sum_i W1[i][j]*W2[j][i]
//  [19] pad
//  [20..35] W2[j][0..15]

__global__ void __launch_bounds__(THREADS, 2)
flow_kernel(const float* __restrict__ x0,
            const float* __restrict__ W1,
            const float* __restrict__ b1,
            const float* __restrict__ W2,
            const float* __restrict__ b2,
            float* __restrict__ out,
            int batch)
{
    __shared__ __align__(16) float sp[64 * ROWF];
    __shared__ __align__(16) float sb2[16];
    __shared__ float s_csum;

    const int tid = threadIdx.x;

    if (tid < 64) {
        const int j = tid;
        float* row = &sp[j * ROWF];
        float c = 0.f;
        #pragma unroll
        for (int i = 0; i < 16; i++) {
            float w1 = W1[i * 64 + j];
            float w2 = W2[j * 16 + i];
            row[i]      = w1;
            row[20 + i] = w2;
            c += w1 * w2;
        }
        float wt = W1[16 * 64 + j];
        float bb = b1[j];
        row[16] = bb;                    // bse at t=0
        row[17] = fmaf(0.5f, wt, bb);    // bse at t=0.5
        row[18] = c;
        row[19] = 0.f;
    } else if (tid < 80) {
        sb2[tid - 64] = b2[tid - 64];
    }
    __syncthreads();
    if (tid == 0) {
        float cs = 0.f;
        #pragma unroll
        for (int j = 0; j < 64; j++) cs += sp[j * ROWF + 18];
        s_csum = cs;
    }
    __syncthreads();
    const float csum = s_csum;

    const int base = blockIdx.x * (THREADS * MSAMP);
    int bs[MSAMP];
    bool has[MSAMP];
    #pragma unroll
    for (int m = 0; m < MSAMP; m++) {
        bs[m]  = base + m * THREADS + tid;
        has[m] = bs[m] < batch;
    }
    if (!has[0]) return;

    u64 X[MSAMP][8];
    const ulonglong2* xin = (const ulonglong2*)x0;
    #pragma unroll
    for (int m = 0; m < MSAMP; m++) {
        int b = has[m] ? bs[m] : bs[0];
        #pragma unroll
        for (int q = 0; q < 4; q++) {
            ulonglong2 t2 = xin[(size_t)b * 4 + q];
            X[m][2 * q]     = t2.x;
            X[m][2 * q + 1] = t2.y;
        }
    }

    const float dt = 0.5f;
    const u64 dt2 = pack2(dt, dt);
    float logq[MSAMP];
    #pragma unroll
    for (int m = 0; m < MSAMP; m++) logq[m] = 0.f;
    const u64* sb2u = (const u64*)sb2;

    #pragma unroll
    for (int s = 0; s < NSTEPS; s++) {
        u64 V[MSAMP][8];
        #pragma unroll
        for (int m = 0; m < MSAMP; m++)
            #pragma unroll
            for (int k = 0; k < 8; k++) V[m][k] = sb2u[k];
        float hc[MSAMP];   // accumulates sum_j h^2 * c_j
        #pragma unroll
        for (int m = 0; m < MSAMP; m++) hc[m] = 0.f;

        #pragma unroll 2
        for (int j = 0; j < 64; j++) {
            const ulonglong2* rp = (const ulonglong2*)&sp[j * ROWF];
            ulonglong2 wa = rp[0];
            ulonglong2 wb = rp[1];
            ulonglong2 wc = rp[2];
            ulonglong2 wd = rp[3];
            float4 aux = ((const float4*)rp)[4];   // bse0, bse1, c, pad
            ulonglong2 va = rp[5];
            ulonglong2 vb = rp[6];
            ulonglong2 vc = rp[7];
            ulonglong2 vd = rp[8];

            const float bse = (s == 0) ? aux.x : aux.y;

            #pragma unroll
            for (int m = 0; m < MSAMP; m++) {
                u64 p0 = mul2(X[m][0], wa.x);
                u64 p1 = mul2(X[m][1], wa.y);
                p0 = fma2(X[m][2], wb.x, p0);
                p1 = fma2(X[m][3], wb.y, p1);
                p0 = fma2(X[m][4], wc.x, p0);
                p1 = fma2(X[m][5], wc.y, p1);
                p0 = fma2(X[m][6], wd.x, p0);
                p1 = fma2(X[m][7], wd.y, p1);
                u64 p = add2(p0, p1);
                float lo, hi; unpack2(p, lo, hi);
                float pre = (lo + hi) + bse;
                float h = fast_tanh(pre);
                hc[m] = fmaf(h * h, aux.z, hc[m]);
                u64 h2 = pack2(h, h);
                V[m][0] = fma2(h2, va.x, V[m][0]);
                V[m][1] = fma2(h2, va.y, V[m][1]);
                V[m][2] = fma2(h2, vb.x, V[m][2]);
                V[m][3] = fma2(h2, vb.y, V[m][3]);
                V[m][4] = fma2(h2, vc.x, V[m][4]);
                V[m][5] = fma2(h2, vc.y, V[m][5]);
                V[m][6] = fma2(h2, vd.x, V[m][6]);
                V[m][7] = fma2(h2, vd.y, V[m][7]);
            }
        }

        #pragma unroll
        for (int m = 0; m < MSAMP; m++) {
            #pragma unroll
            for (int k = 0; k < 8; k++) X[m][k] = fma2(dt2, V[m][k], X[m][k]);
            // div = csum - sum_j h^2 c_j ; logq -= dt*div
            logq[m] -= dt * (csum - hc[m]);
        }
    }

    ulonglong2* outp = (ulonglong2*)out;
    #pragma unroll
    for (int m = 0; m < MSAMP; m++) {
        if (!has[m]) break;
        const int b = bs[m];
        #pragma unroll
        for (int q = 0; q < 4; q++) {
            ulonglong2 t2;
            t2.x = X[m][2 * q];
            t2.y = X[m][2 * q + 1];
            outp[(size_t)b * 4 + q] = t2;
        }
        out[(size_t)batch * 16 + b] = logq[m];
    }
}

extern "C" void kernel_launch(void* const* d_in, const int* in_sizes, int n_in,
                              void* d_out, int out_size) {
    const float* x0 = (const float*)d_in[0];
    const float* W1 = (const float*)d_in[1];
    const float* b1 = (const float*)d_in[2];
    const float* W2 = (const float*)d_in[3];
    const float* b2 = (const float*)d_in[4];
    float* out = (float*)d_out;

    const int batch = in_sizes[0] / 16;
    const int per_block = THREADS * MSAMP;
    const int blocks = (batch + per_block - 1) / per_block;
    flow_kernel<<<blocks, THREADS>>>(x0, W1, b1, W2, b2, out, batch);
}